// round 4
// baseline (speedup 1.0000x reference)
#include <cuda_runtime.h>
#include <cuda_fp16.h>
#include <cstdint>

// Problem shape (fixed by setup_inputs): B=32, S=256, H=768
#define NB 32
#define NS 256
#define NH 768
#define ROW_U4 (NH/8)   // 96 uint4 (fp16) per token row

// ---------------- scratch (static device globals; no allocation) ----------------
__device__ uint4 g_qn4[NB*NS*ROW_U4];     // normalized Q, fp16
__device__ uint4 g_kn4[NB*NS*ROW_U4];     // normalized K, fp16
__device__ float g_wtab[NS];              // scale * exp(-alpha * d)
__device__ float g_invden[NB];            // 1 / clip(sum q_mask, 1)
__device__ float g_partial[2*NB*NB];      // per-mtile partials (deterministic)

// ---------------- helpers ----------------
static __device__ __forceinline__ uint32_t smem_u32(const void* p) {
    uint32_t a;
    asm("{ .reg .u64 t; cvta.to.shared.u64 t, %1; cvt.u32.u64 %0, t; }" : "=r"(a) : "l"(p));
    return a;
}
#define CP_ASYNC16(dst_s32, src_gen) \
    asm volatile("cp.async.cg.shared.global [%0], [%1], 16;" \
                 :: "r"(dst_s32), "l"(__cvta_generic_to_global(src_gen)) : "memory")
#define CP_COMMIT() asm volatile("cp.async.commit_group;" ::: "memory")
#define CP_WAIT(n)  asm volatile("cp.async.wait_group %0;" :: "n"(n) : "memory")
#define LDSM4(r0,r1,r2,r3,addr) \
    asm volatile("ldmatrix.sync.aligned.m8n8.x4.shared.b16 {%0,%1,%2,%3}, [%4];" \
                 : "=r"(r0), "=r"(r1), "=r"(r2), "=r"(r3) : "r"(addr))

static __device__ __forceinline__ void mma16816(float c[4],
                                                uint32_t a0, uint32_t a1, uint32_t a2, uint32_t a3,
                                                uint32_t b0, uint32_t b1) {
    asm volatile("mma.sync.aligned.m16n8k16.row.col.f32.f16.f16.f32 "
                 "{%0,%1,%2,%3}, {%4,%5,%6,%7}, {%8,%9}, {%0,%1,%2,%3};"
                 : "+f"(c[0]), "+f"(c[1]), "+f"(c[2]), "+f"(c[3])
                 : "r"(a0), "r"(a1), "r"(a2), "r"(a3), "r"(b0), "r"(b1));
}

// ---------------- kernel 1: scalars ----------------
__global__ void __launch_bounds__(256) prep_kernel(const float* __restrict__ ar,
                                                   const float* __restrict__ ls,
                                                   const float* __restrict__ qm) {
    int tid = threadIdx.x;
    float a = ar[0];
    float alpha = (a > 15.f) ? a : log1pf(expf(a));   // softplus
    float scale = expf(ls[0]);
    g_wtab[tid] = scale * expf(-alpha * (float)tid);
    __shared__ float ws[8];
    for (int i = 0; i < NB; i++) {
        float v = qm[i*NS + tid];
        #pragma unroll
        for (int o = 16; o; o >>= 1) v += __shfl_xor_sync(0xffffffffu, v, o);
        if ((tid & 31) == 0) ws[tid >> 5] = v;
        __syncthreads();
        if (tid == 0) {
            float s = 0.f;
            #pragma unroll
            for (int w = 0; w < 8; w++) s += ws[w];
            g_invden[i] = 1.f / fmaxf(s, 1.f);
        }
        __syncthreads();
    }
}

// ---------------- kernel 2: L2-normalize -> fp16 ----------------
__global__ void __launch_bounds__(256) normalize_kernel(const float* __restrict__ q,
                                                        const float* __restrict__ k) {
    int row = blockIdx.x, tid = threadIdx.x;
    const float* src = blockIdx.y ? k : q;
    half* dst = (half*)(blockIdx.y ? g_kn4 : g_qn4);
    float x0 = src[row*NH + tid];
    float x1 = src[row*NH + 256 + tid];
    float x2 = src[row*NH + 512 + tid];
    float ss = x0*x0 + x1*x1 + x2*x2;
    #pragma unroll
    for (int o = 16; o; o >>= 1) ss += __shfl_xor_sync(0xffffffffu, ss, o);
    __shared__ float ws[8];
    __shared__ float s_inv;
    if ((tid & 31) == 0) ws[tid >> 5] = ss;
    __syncthreads();
    if (tid == 0) {
        float s = 0.f;
        #pragma unroll
        for (int w = 0; w < 8; w++) s += ws[w];
        s_inv = 1.f / fmaxf(sqrtf(s), 1e-12f);
    }
    __syncthreads();
    float inv = s_inv;
    dst[row*NH + tid]       = __float2half_rn(x0 * inv);
    dst[row*NH + 256 + tid] = __float2half_rn(x1 * inv);
    dst[row*NH + 512 + tid] = __float2half_rn(x2 * inv);
}

// ---------------- kernel 3: fused GEMM + decayed softmax score ----------------
// CTA tile: 128 (M) x 256 (N), K=768 in 12 chunks of 64 halves.
// 512 threads = 16 warps, warp grid 2(M) x 8(N), warp tile 64x32.
// 3-stage cp.async pipeline, one __syncthreads per chunk, ldmatrix fragments.
#define OFF_KM   1024
#define OFF_RED  2048      // red_n[8][128], red_d[8][128] -> 8192 bytes
#define OFF_TILE 10240
#define PITCHB   144       // 72 halves per row (64 data + 8 pad)
#define A_BYTES  (128*PITCHB)    // 18432
#define STAGE    (384*PITCHB)    // A+B = 55296
#define NSTAGE   3
#define SMEM_BYTES (OFF_TILE + NSTAGE*STAGE)   // 176128
#define KCHUNKS 12

__global__ void __launch_bounds__(512, 1) li_main(const float* __restrict__ qmask,
                                                  const float* __restrict__ kmask) {
    extern __shared__ __align__(1024) char smem[];
    const int tid  = threadIdx.x;
    const int lane = tid & 31, wid = tid >> 5;
    const int wm = wid >> 3, wn = wid & 7;          // 2 x 8 warp grid
    const int lr = lane >> 2;                       // 0..7
    const int j = blockIdx.x, i = blockIdx.y, mt = blockIdx.z;

    float* wtab_s = (float*)smem;
    float* km_s   = (float*)(smem + OFF_KM);
    float* red_n  = (float*)(smem + OFF_RED);           // [8][128]
    float* red_d  = (float*)(smem + OFF_RED + 4096);    // [8][128]
    const uint32_t sb = smem_u32(smem);

    for (int c = tid; c < NS; c += 512) {
        wtab_s[c] = g_wtab[c];
        km_s[c]   = kmask[j*NS + c];
    }

    const int qrow0 = i*NS + mt*128;
    const int krow0 = j*NS;

    // per-lane ldmatrix address components (quadrant mapping -> mma frag order)
    const int lq  = lane >> 3;                      // quadrant 0..3
    const int l7  = lane & 7;
    const uint32_t aOff = (uint32_t)(((lq & 1)*8 + l7)*PITCHB + (lq >> 1)*16);
    const uint32_t bOff = (uint32_t)(((lq >> 1)*8 + l7)*PITCHB + (lq & 1)*16);

    // ---- async tile loader (one K-chunk of 64 halves) ----
    auto load_chunk = [&](int kc, int b) {
        uint32_t sA = sb + OFF_TILE + b*STAGE;
        uint32_t sB = sA + A_BYTES;
        #pragma unroll
        for (int w = 0; w < 2; w++) {               // A: 1024 uint4
            int idx = tid + w*512, r = idx >> 3, v = idx & 7;
            CP_ASYNC16(sA + (uint32_t)(r*PITCHB + v*16),
                       &g_qn4[(qrow0 + r)*ROW_U4 + kc*8 + v]);
        }
        #pragma unroll
        for (int w = 0; w < 4; w++) {               // B: 2048 uint4
            int idx = tid + w*512, r = idx >> 3, v = idx & 7;
            CP_ASYNC16(sB + (uint32_t)(r*PITCHB + v*16),
                       &g_kn4[(krow0 + r)*ROW_U4 + kc*8 + v]);
        }
        CP_COMMIT();
    };

    float c[4][4][4];
    #pragma unroll
    for (int mi = 0; mi < 4; mi++)
        #pragma unroll
        for (int ni = 0; ni < 4; ni++)
            #pragma unroll
            for (int r = 0; r < 4; r++) c[mi][ni][r] = 0.f;

    load_chunk(0, 0);
    load_chunk(1, 1);

    for (int kc = 0; kc < KCHUNKS; kc++) {
        const int b = kc % 3;
        if (kc < KCHUNKS-1) CP_WAIT(1); else CP_WAIT(0);
        __syncthreads();
        if (kc + 2 < KCHUNKS) load_chunk(kc + 2, (kc + 2) % 3);

        const uint32_t sA = sb + OFF_TILE + b*STAGE + (uint32_t)(wm*64)*PITCHB + aOff;
        const uint32_t sB = sb + OFF_TILE + b*STAGE + A_BYTES + (uint32_t)(wn*32)*PITCHB + bOff;

        #pragma unroll
        for (int ks = 0; ks < 4; ks++) {
            const uint32_t ko = ks*32;
            uint32_t a[4][4];
            #pragma unroll
            for (int mi = 0; mi < 4; mi++)
                LDSM4(a[mi][0], a[mi][1], a[mi][2], a[mi][3],
                      sA + (uint32_t)(mi*16)*PITCHB + ko);
            uint32_t bb[2][4];
            #pragma unroll
            for (int nb = 0; nb < 2; nb++)
                LDSM4(bb[nb][0], bb[nb][1], bb[nb][2], bb[nb][3],
                      sB + (uint32_t)(nb*16)*PITCHB + ko);
            #pragma unroll
            for (int mi = 0; mi < 4; mi++)
                #pragma unroll
                for (int ni = 0; ni < 4; ni++)
                    mma16816(c[mi][ni],
                             a[mi][0], a[mi][1], a[mi][2], a[mi][3],
                             bb[ni >> 1][(ni & 1)*2], bb[ni >> 1][(ni & 1)*2 + 1]);
        }
    }
    __syncthreads();

    // ---- epilogue: decayed softmax-weighted score ----
    // element (mi,ni,r): row m = wm*64 + mi*16 + 8*(r>>1) + lr
    //                    col t = wn*32 + ni*8 + (lane&3)*2 + (r&1)
    float num[8], den[8];                           // slot = mi*2 + rh
    #pragma unroll
    for (int s = 0; s < 8; s++) { num[s] = 0.f; den[s] = 0.f; }

    const int s_base = mt*128 + wm*64 + lr;
    const int t_base = wn*32 + (lane & 3)*2;
    #pragma unroll
    for (int mi = 0; mi < 4; mi++) {
        #pragma unroll
        for (int rh = 0; rh < 2; rh++) {
            const int s_tok = s_base + mi*16 + 8*rh;
            const int slot = mi*2 + rh;
            #pragma unroll
            for (int ni = 0; ni < 4; ni++) {
                #pragma unroll
                for (int rl = 0; rl < 2; rl++) {
                    float sim = c[mi][ni][rh*2 + rl];
                    int t = t_base + ni*8 + rl;
                    int d = (s_tok > t) ? (s_tok - t) : (t - s_tok);
                    float e = __expf(wtab_s[d] * sim);
                    e = (km_s[t] > 0.f) ? e : 0.f;
                    num[slot] = fmaf(e, sim, num[slot]);
                    den[slot] += e;
                }
            }
        }
    }
    #pragma unroll
    for (int o = 1; o <= 2; o <<= 1) {
        #pragma unroll
        for (int s = 0; s < 8; s++) {
            num[s] += __shfl_xor_sync(0xffffffffu, num[s], o);
            den[s] += __shfl_xor_sync(0xffffffffu, den[s], o);
        }
    }
    if ((lane & 3) == 0) {
        #pragma unroll
        for (int mi = 0; mi < 4; mi++)
            #pragma unroll
            for (int rh = 0; rh < 2; rh++) {
                int row = wm*64 + mi*16 + 8*rh + lr;
                red_n[wn*128 + row] = num[mi*2 + rh];
                red_d[wn*128 + row] = den[mi*2 + rh];
            }
    }
    __syncthreads();

    if (tid < 128) {
        float n2 = 0.f, d2 = 0.f;
        #pragma unroll
        for (int w = 0; w < 8; w++) { n2 += red_n[w*128 + tid]; d2 += red_d[w*128 + tid]; }
        float qm = qmask[i*NS + mt*128 + tid];
        float score = (d2 > 0.f) ? (n2 / d2) * qm : 0.f;
        red_n[tid] = score;
    }
    __syncthreads();
    if (tid < 32) {
        float s2 = red_n[tid] + red_n[tid + 32] + red_n[tid + 64] + red_n[tid + 96];
        #pragma unroll
        for (int o = 16; o; o >>= 1) s2 += __shfl_xor_sync(0xffffffffu, s2, o);
        if (tid == 0) g_partial[mt*(NB*NB) + i*NB + j] = s2 * g_invden[i];
    }
}

// ---------------- kernel 4: deterministic finalize ----------------
__global__ void finalize_kernel(float* __restrict__ out) {
    int x = blockIdx.x * blockDim.x + threadIdx.x;    // 1024
    out[x] = g_partial[x] + g_partial[NB*NB + x];
}

// ---------------- launch ----------------
extern "C" void kernel_launch(void* const* d_in, const int* in_sizes, int n_in,
                              void* d_out, int out_size) {
    const float* q  = (const float*)d_in[0];
    const float* k  = (const float*)d_in[1];
    const float* qm = (const float*)d_in[2];
    const float* km = (const float*)d_in[3];
    const float* ar = (const float*)d_in[4];
    const float* ls = (const float*)d_in[5];
    float* out = (float*)d_out;

    prep_kernel<<<1, 256>>>(ar, ls, qm);
    normalize_kernel<<<dim3(NB*NS, 2), 256>>>(q, k);

    static int smem_set = 0;
    if (!smem_set) {
        cudaFuncSetAttribute(li_main, cudaFuncAttributeMaxDynamicSharedMemorySize, SMEM_BYTES);
        smem_set = 1;
    }
    li_main<<<dim3(NB, NB, 2), 512, SMEM_BYTES>>>(qm, km);

    finalize_kernel<<<4, 256>>>(out);
}

// round 5
// speedup vs baseline: 1.4928x; 1.4928x over previous
#include <cuda_runtime.h>
#include <cuda_fp16.h>
#include <cstdint>

// Problem shape (fixed by setup_inputs): B=32, S=256, H=768
#define NB 32
#define NS 256
#define NH 768
#define ROW_U4 (NH/8)   // 96 uint4 (fp16) per token row

// ---------------- scratch (static device globals; no allocation) ----------------
__device__ uint4 g_qn4[NB*NS*ROW_U4];     // normalized Q, fp16
__device__ uint4 g_kn4[NB*NS*ROW_U4];     // normalized K, fp16
__device__ float g_wtab[NS];              // scale * exp(-alpha * d)
__device__ float g_invden[NB];            // 1 / clip(sum q_mask, 1)
__device__ float g_partial[2*NB*NB];      // per-mtile partials (deterministic)

// ---------------- helpers ----------------
static __device__ __forceinline__ uint32_t smem_u32(const void* p) {
    uint32_t a;
    asm("{ .reg .u64 t; cvta.to.shared.u64 t, %1; cvt.u32.u64 %0, t; }" : "=r"(a) : "l"(p));
    return a;
}
#define CP_ASYNC16(dst_s32, src_gen) \
    asm volatile("cp.async.cg.shared.global [%0], [%1], 16;" \
                 :: "r"(dst_s32), "l"(__cvta_generic_to_global(src_gen)) : "memory")
#define CP_COMMIT() asm volatile("cp.async.commit_group;" ::: "memory")
#define CP_WAIT(n)  asm volatile("cp.async.wait_group %0;" :: "n"(n) : "memory")
#define LDSM4(r0,r1,r2,r3,addr) \
    asm volatile("ldmatrix.sync.aligned.m8n8.x4.shared.b16 {%0,%1,%2,%3}, [%4];" \
                 : "=r"(r0), "=r"(r1), "=r"(r2), "=r"(r3) : "r"(addr))

static __device__ __forceinline__ void mma16816(float c[4],
                                                uint32_t a0, uint32_t a1, uint32_t a2, uint32_t a3,
                                                uint32_t b0, uint32_t b1) {
    asm volatile("mma.sync.aligned.m16n8k16.row.col.f32.f16.f16.f32 "
                 "{%0,%1,%2,%3}, {%4,%5,%6,%7}, {%8,%9}, {%0,%1,%2,%3};"
                 : "+f"(c[0]), "+f"(c[1]), "+f"(c[2]), "+f"(c[3])
                 : "r"(a0), "r"(a1), "r"(a2), "r"(a3), "r"(b0), "r"(b1));
}

// ---------------- kernel 1: scalars ----------------
__global__ void __launch_bounds__(256) prep_kernel(const float* __restrict__ ar,
                                                   const float* __restrict__ ls,
                                                   const float* __restrict__ qm) {
    int tid = threadIdx.x;
    float a = ar[0];
    float alpha = (a > 15.f) ? a : log1pf(expf(a));   // softplus
    float scale = expf(ls[0]);
    g_wtab[tid] = scale * expf(-alpha * (float)tid);
    __shared__ float ws[8];
    for (int i = 0; i < NB; i++) {
        float v = qm[i*NS + tid];
        #pragma unroll
        for (int o = 16; o; o >>= 1) v += __shfl_xor_sync(0xffffffffu, v, o);
        if ((tid & 31) == 0) ws[tid >> 5] = v;
        __syncthreads();
        if (tid == 0) {
            float s = 0.f;
            #pragma unroll
            for (int w = 0; w < 8; w++) s += ws[w];
            g_invden[i] = 1.f / fmaxf(s, 1.f);
        }
        __syncthreads();
    }
}

// ---------------- kernel 2: L2-normalize -> fp16 ----------------
__global__ void __launch_bounds__(256) normalize_kernel(const float* __restrict__ q,
                                                        const float* __restrict__ k) {
    int row = blockIdx.x, tid = threadIdx.x;
    const float* src = blockIdx.y ? k : q;
    half* dst = (half*)(blockIdx.y ? g_kn4 : g_qn4);
    float x0 = src[row*NH + tid];
    float x1 = src[row*NH + 256 + tid];
    float x2 = src[row*NH + 512 + tid];
    float ss = x0*x0 + x1*x1 + x2*x2;
    #pragma unroll
    for (int o = 16; o; o >>= 1) ss += __shfl_xor_sync(0xffffffffu, ss, o);
    __shared__ float ws[8];
    __shared__ float s_inv;
    if ((tid & 31) == 0) ws[tid >> 5] = ss;
    __syncthreads();
    if (tid == 0) {
        float s = 0.f;
        #pragma unroll
        for (int w = 0; w < 8; w++) s += ws[w];
        s_inv = 1.f / fmaxf(sqrtf(s), 1e-12f);
    }
    __syncthreads();
    float inv = s_inv;
    dst[row*NH + tid]       = __float2half_rn(x0 * inv);
    dst[row*NH + 256 + tid] = __float2half_rn(x1 * inv);
    dst[row*NH + 512 + tid] = __float2half_rn(x2 * inv);
}

// ---------------- kernel 3: fused GEMM + decayed softmax score ----------------
// CTA tile: 128 (M) x 256 (N), K=768 in 12 chunks of 64 halves.
// 256 threads = 8 warps, warp grid 2(M) x 4(N), warp tile 64x64 (minimal smem traffic).
// 3-stage cp.async pipeline, ONE __syncthreads per chunk, ldmatrix fragments.
#define OFF_KM   1024
#define OFF_RED  2048      // red_n[4][128], red_d[4][128] -> 4096 bytes
#define OFF_TILE 6144
#define PITCHB   144       // 72 halves per row (64 data + 8 pad)
#define A_BYTES  (128*PITCHB)    // 18432
#define STAGE    (384*PITCHB)    // A+B = 55296
#define NSTAGE   3
#define SMEM_BYTES (OFF_TILE + NSTAGE*STAGE)   // 172032
#define KCHUNKS 12

__global__ void __launch_bounds__(256, 1) li_main(const float* __restrict__ qmask,
                                                  const float* __restrict__ kmask) {
    extern __shared__ __align__(1024) char smem[];
    const int tid  = threadIdx.x;
    const int lane = tid & 31, wid = tid >> 5;
    const int wm = wid >> 2, wn = wid & 3;          // 2 x 4 warp grid
    const int lr = lane >> 2;                       // 0..7
    const int j = blockIdx.x, i = blockIdx.y, mt = blockIdx.z;

    float* wtab_s = (float*)smem;
    float* km_s   = (float*)(smem + OFF_KM);
    float* red_n  = (float*)(smem + OFF_RED);           // [4][128]
    float* red_d  = (float*)(smem + OFF_RED + 2048);    // [4][128]
    const uint32_t sb = smem_u32(smem);

    for (int c = tid; c < NS; c += 256) {
        wtab_s[c] = g_wtab[c];
        km_s[c]   = kmask[j*NS + c];
    }

    const int qrow0 = i*NS + mt*128;
    const int krow0 = j*NS;

    // per-lane ldmatrix address components (quadrant mapping -> mma frag order)
    // (validated in round 3: identical rel_err)
    const int lq  = lane >> 3;                      // quadrant 0..3
    const int l7  = lane & 7;
    const uint32_t aOff = (uint32_t)(((lq & 1)*8 + l7)*PITCHB + (lq >> 1)*16);
    const uint32_t bOff = (uint32_t)(((lq >> 1)*8 + l7)*PITCHB + (lq & 1)*16);

    // ---- async tile loader (one K-chunk of 64 halves) ----
    auto load_chunk = [&](int kc, int b) {
        uint32_t sA = sb + OFF_TILE + b*STAGE;
        uint32_t sB = sA + A_BYTES;
        #pragma unroll
        for (int w = 0; w < 4; w++) {               // A: 1024 uint4
            int idx = tid + w*256, r = idx >> 3, v = idx & 7;
            CP_ASYNC16(sA + (uint32_t)(r*PITCHB + v*16),
                       &g_qn4[(qrow0 + r)*ROW_U4 + kc*8 + v]);
        }
        #pragma unroll
        for (int w = 0; w < 8; w++) {               // B: 2048 uint4
            int idx = tid + w*256, r = idx >> 3, v = idx & 7;
            CP_ASYNC16(sB + (uint32_t)(r*PITCHB + v*16),
                       &g_kn4[(krow0 + r)*ROW_U4 + kc*8 + v]);
        }
        CP_COMMIT();
    };

    float c[4][8][4];
    #pragma unroll
    for (int mi = 0; mi < 4; mi++)
        #pragma unroll
        for (int ni = 0; ni < 8; ni++)
            #pragma unroll
            for (int r = 0; r < 4; r++) c[mi][ni][r] = 0.f;

    load_chunk(0, 0);
    load_chunk(1, 1);

    for (int kc = 0; kc < KCHUNKS; kc++) {
        const int b = kc % 3;
        if (kc < KCHUNKS-1) CP_WAIT(1); else CP_WAIT(0);
        __syncthreads();
        if (kc + 2 < KCHUNKS) load_chunk(kc + 2, (kc + 2) % 3);

        const uint32_t sA = sb + OFF_TILE + b*STAGE + (uint32_t)(wm*64)*PITCHB + aOff;
        const uint32_t sB = sb + OFF_TILE + b*STAGE + A_BYTES + (uint32_t)(wn*64)*PITCHB + bOff;

        #pragma unroll
        for (int ks = 0; ks < 4; ks++) {
            const uint32_t ko = ks*32;
            uint32_t a[4][4];
            #pragma unroll
            for (int mi = 0; mi < 4; mi++)
                LDSM4(a[mi][0], a[mi][1], a[mi][2], a[mi][3],
                      sA + (uint32_t)(mi*16)*PITCHB + ko);
            uint32_t bb[4][4];
            #pragma unroll
            for (int nb = 0; nb < 4; nb++)
                LDSM4(bb[nb][0], bb[nb][1], bb[nb][2], bb[nb][3],
                      sB + (uint32_t)(nb*16)*PITCHB + ko);
            #pragma unroll
            for (int mi = 0; mi < 4; mi++)
                #pragma unroll
                for (int ni = 0; ni < 8; ni++)
                    mma16816(c[mi][ni],
                             a[mi][0], a[mi][1], a[mi][2], a[mi][3],
                             bb[ni >> 1][(ni & 1)*2], bb[ni >> 1][(ni & 1)*2 + 1]);
        }
    }
    __syncthreads();

    // ---- epilogue: decayed softmax-weighted score ----
    // element (mi,ni,r): row m = wm*64 + mi*16 + 8*(r>>1) + lr
    //                    col t = wn*64 + ni*8 + (lane&3)*2 + (r&1)
    float num[8], den[8];                           // slot = mi*2 + rh
    #pragma unroll
    for (int s = 0; s < 8; s++) { num[s] = 0.f; den[s] = 0.f; }

    const int s_base = mt*128 + wm*64 + lr;
    const int t_base = wn*64 + (lane & 3)*2;
    #pragma unroll
    for (int mi = 0; mi < 4; mi++) {
        #pragma unroll
        for (int rh = 0; rh < 2; rh++) {
            const int s_tok = s_base + mi*16 + 8*rh;
            const int slot = mi*2 + rh;
            #pragma unroll
            for (int ni = 0; ni < 8; ni++) {
                #pragma unroll
                for (int rl = 0; rl < 2; rl++) {
                    float sim = c[mi][ni][rh*2 + rl];
                    int t = t_base + ni*8 + rl;
                    int d = (s_tok > t) ? (s_tok - t) : (t - s_tok);
                    float e = __expf(wtab_s[d] * sim);
                    e = (km_s[t] > 0.f) ? e : 0.f;
                    num[slot] = fmaf(e, sim, num[slot]);
                    den[slot] += e;
                }
            }
        }
    }
    #pragma unroll
    for (int o = 1; o <= 2; o <<= 1) {
        #pragma unroll
        for (int s = 0; s < 8; s++) {
            num[s] += __shfl_xor_sync(0xffffffffu, num[s], o);
            den[s] += __shfl_xor_sync(0xffffffffu, den[s], o);
        }
    }
    if ((lane & 3) == 0) {
        #pragma unroll
        for (int mi = 0; mi < 4; mi++)
            #pragma unroll
            for (int rh = 0; rh < 2; rh++) {
                int row = wm*64 + mi*16 + 8*rh + lr;
                red_n[wn*128 + row] = num[mi*2 + rh];
                red_d[wn*128 + row] = den[mi*2 + rh];
            }
    }
    __syncthreads();

    if (tid < 128) {
        float n2 = red_n[tid] + red_n[128 + tid] + red_n[256 + tid] + red_n[384 + tid];
        float d2 = red_d[tid] + red_d[128 + tid] + red_d[256 + tid] + red_d[384 + tid];
        float qm = qmask[i*NS + mt*128 + tid];
        float score = (d2 > 0.f) ? (n2 / d2) * qm : 0.f;
        red_n[tid] = score;
    }
    __syncthreads();
    if (tid < 32) {
        float s2 = red_n[tid] + red_n[tid + 32] + red_n[tid + 64] + red_n[tid + 96];
        #pragma unroll
        for (int o = 16; o; o >>= 1) s2 += __shfl_xor_sync(0xffffffffu, s2, o);
        if (tid == 0) g_partial[mt*(NB*NB) + i*NB + j] = s2 * g_invden[i];
    }
}

// ---------------- kernel 4: deterministic finalize ----------------
__global__ void finalize_kernel(float* __restrict__ out) {
    int x = blockIdx.x * blockDim.x + threadIdx.x;    // 1024
    out[x] = g_partial[x] + g_partial[NB*NB + x];
}

// ---------------- launch ----------------
extern "C" void kernel_launch(void* const* d_in, const int* in_sizes, int n_in,
                              void* d_out, int out_size) {
    const float* q  = (const float*)d_in[0];
    const float* k  = (const float*)d_in[1];
    const float* qm = (const float*)d_in[2];
    const float* km = (const float*)d_in[3];
    const float* ar = (const float*)d_in[4];
    const float* ls = (const float*)d_in[5];
    float* out = (float*)d_out;

    prep_kernel<<<1, 256>>>(ar, ls, qm);
    normalize_kernel<<<dim3(NB*NS, 2), 256>>>(q, k);

    static int smem_set = 0;
    if (!smem_set) {
        cudaFuncSetAttribute(li_main, cudaFuncAttributeMaxDynamicSharedMemorySize, SMEM_BYTES);
        smem_set = 1;
    }
    li_main<<<dim3(NB, NB, 2), 256, SMEM_BYTES>>>(qm, km);

    finalize_kernel<<<4, 256>>>(out);
}